// round 14
// baseline (speedup 1.0000x reference)
#include <cuda_runtime.h>

// QuantumConv1d — single fused kernel (3rd attempt; root cause of prior failures
// was the Q-fold's 64+ register footprint taxing every warp).
//  - Lane-distributed Q fold on warp 0: 16 amplitudes x 4 columns spread over 32
//    lanes (2 complex values/lane), gates via shfl_xor, CNOTs folded into Z-signs
//    -> ~38 live regs instead of ~80.
//  - Warps 1-15 stage the x tile + weights concurrently.
//  - Quad-split conv (R6-proven) -> ez_s in smem (no global round-trip).
//  - Store phase identical to the measured-best writer (float4 __stcs, o-stride 16).
//  __launch_bounds__(512,3): <=42 regs -> 3 CTAs/SM, writer-level occupancy.

#define C_IN     80
#define L_IN     3000
#define OUT_CH   512
#define KW       3
#define TILE_L   128
#define THREADS  512
#define C_PER_G  (C_IN / 4)           // 20 channels per quad lane

__global__ __launch_bounds__(THREADS, 3)
void qconv_fused(const float* __restrict__ x,
                 const float* __restrict__ W_pre,
                 const float* __restrict__ b_pre,
                 const float* __restrict__ W_post,
                 const float* __restrict__ b_post,
                 const float* __restrict__ qw,
                 float* __restrict__ out)
{
    __shared__ float x_s[C_IN][130];        // j=0 <-> l0-1 .. j=129 <-> l0+128; 41.6KB
    __shared__ float w_s[C_IN * 12];        // [c][k][q] 3.75 KB
    __shared__ float ez_s[TILE_L][4];       // 2 KB
    __shared__ float Q_s[4][16];            // 256 B
    __shared__ float bpre_s[4];

    const int tid = threadIdx.x;
    const int b   = blockIdx.y;
    const int l0  = blockIdx.x * TILE_L;

    // ======== Phase 0: lane-distributed Q fold (warp 0) || staging (warps 1-15) ======
    if (tid < 32) {
        const int lane = tid;
        const int jm   = lane >> 2;         // j mod 8
        const int k    = lane & 3;          // basis column
        // slot0: index i0 = jm ; slot1: index i1 = jm + 8
        float ar0 = (jm == k) ? 1.f : 0.f, ai0 = 0.f;
        float ar1 = 0.f,                   ai1 = 0.f;

        // ---- wire 0 (s=8): pair (i0,i1) is in-lane ----
        {
            float phi = __ldg(qw + 0), th = __ldg(qw + 1), om = __ldg(qw + 2);
            float sh, ch; __sincosf(0.5f * th, &sh, &ch);
            float a = 0.5f * (phi + om), d = 0.5f * (phi - om);
            float sa, ca, sd, cd;
            __sincosf(a, &sa, &ca); __sincosf(d, &sd, &cd);
            float u00r =  ch * ca, u00i = -ch * sa;
            float u01r = -sh * cd, u01i = -sh * sd;
            float u10r =  sh * cd, u10i = -sh * sd;
            float u11r =  ch * ca, u11i =  ch * sa;
            float n0r = u00r*ar0 - u00i*ai0 + u01r*ar1 - u01i*ai1;
            float n0i = u00r*ai0 + u00i*ar0 + u01r*ai1 + u01i*ar1;
            float n1r = u10r*ar0 - u10i*ai0 + u11r*ar1 - u11i*ai1;
            float n1i = u10r*ai0 + u10i*ar0 + u11r*ai1 + u11i*ar1;
            ar0 = n0r; ai0 = n0i; ar1 = n1r; ai1 = n1i;
        }
        // ---- wires 1..3 (s=4,2,1): partner lane = lane ^ (4s) ----
        #pragma unroll
        for (int w = 1; w < 4; w++) {
            float phi = __ldg(qw + w * 3 + 0), th = __ldg(qw + w * 3 + 1), om = __ldg(qw + w * 3 + 2);
            float sh, ch; __sincosf(0.5f * th, &sh, &ch);
            float a = 0.5f * (phi + om), d = 0.5f * (phi - om);
            float sa, ca, sd, cd;
            __sincosf(a, &sa, &ca); __sincosf(d, &sd, &cd);
            float u00r =  ch * ca, u00i = -ch * sa;
            float u01r = -sh * cd, u01i = -sh * sd;
            float u10r =  sh * cd, u10i = -sh * sd;
            float u11r =  ch * ca, u11i =  ch * sa;
            const int s = 8 >> w;
            float p0r = __shfl_xor_sync(0xffffffffu, ar0, 4 * s);
            float p0i = __shfl_xor_sync(0xffffffffu, ai0, 4 * s);
            float p1r = __shfl_xor_sync(0xffffffffu, ar1, 4 * s);
            float p1i = __shfl_xor_sync(0xffffffffu, ai1, 4 * s);
            float n0r, n0i, n1r, n1i;
            if ((jm & s) == 0) {            // lower index: u00*self + u01*partner
                n0r = u00r*ar0 - u00i*ai0 + u01r*p0r - u01i*p0i;
                n0i = u00r*ai0 + u00i*ar0 + u01r*p0i + u01i*p0r;
                n1r = u00r*ar1 - u00i*ai1 + u01r*p1r - u01i*p1i;
                n1i = u00r*ai1 + u00i*ar1 + u01r*p1i + u01i*p1r;
            } else {                        // upper index: u10*partner + u11*self
                n0r = u10r*p0r - u10i*p0i + u11r*ar0 - u11i*ai0;
                n0i = u10r*p0i + u10i*p0r + u11r*ai0 + u11i*ar0;
                n1r = u10r*p1r - u10i*p1i + u11r*ar1 - u11i*ai1;
                n1i = u10r*p1i + u10i*p1r + u11r*ai1 + u11i*ar1;
            }
            ar0 = n0r; ai0 = n0i; ar1 = n1r; ai1 = n1i;
        }

        // CNOT chain folded into final index remap f(i):
        //   cnot(0,1): bit3 -> flip bit2; cnot(1,2): bit2 -> flip bit1; cnot(2,3): bit1 -> flip bit0
        int f0 = jm;                        // bit3 clear: first cnot no-op
        if (f0 & 4) f0 ^= 2;
        if (f0 & 2) f0 ^= 1;
        int f1 = (jm + 8) ^ 4;              // bit3 set: flip bit2
        if (f1 & 4) f1 ^= 2;
        if (f1 & 2) f1 ^= 1;

        // Q[q][k][m] partials: lane holds column k; fetch column m from lane group
        float Qa[4][4];
        #pragma unroll
        for (int m = 0; m < 4; m++) {
            const int src = (lane & ~3) | m;
            float a0rm = __shfl_sync(0xffffffffu, ar0, src);
            float a0im = __shfl_sync(0xffffffffu, ai0, src);
            float a1rm = __shfl_sync(0xffffffffu, ar1, src);
            float a1im = __shfl_sync(0xffffffffu, ai1, src);
            float p0 = ar0 * a0rm + ai0 * a0im;
            float p1 = ar1 * a1rm + ai1 * a1im;
            Qa[0][m] = ((f0 & 8) ? -p0 : p0) + ((f1 & 8) ? -p1 : p1);
            Qa[1][m] = ((f0 & 4) ? -p0 : p0) + ((f1 & 4) ? -p1 : p1);
            Qa[2][m] = ((f0 & 2) ? -p0 : p0) + ((f1 & 2) ? -p1 : p1);
            Qa[3][m] = ((f0 & 1) ? -p0 : p0) + ((f1 & 1) ? -p1 : p1);
        }
        // reduce over jm (8 groups at lane stride 4)
        #pragma unroll
        for (int q = 0; q < 4; q++)
            #pragma unroll
            for (int m = 0; m < 4; m++) {
                float v = Qa[q][m];
                v += __shfl_xor_sync(0xffffffffu, v, 4);
                v += __shfl_xor_sync(0xffffffffu, v, 8);
                v += __shfl_xor_sync(0xffffffffu, v, 16);
                Qa[q][m] = v;
            }
        if (lane < 4) {
            #pragma unroll
            for (int q = 0; q < 4; q++)
                #pragma unroll
                for (int m = 0; m < 4; m++)
                    Q_s[q][lane * 4 + m] = Qa[q][m];
        }
    } else {
        const int t = tid - 32;                     // 0..479
        for (int i = t; i < C_IN * 12; i += THREADS - 32) {
            int c = i / 12; int r = i - c * 12; int k = r >> 2; int q = r & 3;
            w_s[i] = W_pre[q * (C_IN * KW) + c * KW + k];
        }
        if (t < 4) bpre_s[t] = b_pre[t];

        const float* xb = x + (size_t)b * C_IN * L_IN;
        // interior j = 1..128 <-> l = l0..l0+127 (aligned float4 global reads)
        for (int i = t; i < C_IN * 32; i += THREADS - 32) {
            int c  = i >> 5;
            int qq = i & 31;
            int l  = l0 + qq * 4;
            float4 vv;
            if (l + 3 < L_IN) {
                vv = *(const float4*)(xb + (size_t)c * L_IN + l);
            } else {
                vv.x = (l + 0 < L_IN) ? xb[(size_t)c * L_IN + l + 0] : 0.f;
                vv.y = (l + 1 < L_IN) ? xb[(size_t)c * L_IN + l + 1] : 0.f;
                vv.z = (l + 2 < L_IN) ? xb[(size_t)c * L_IN + l + 2] : 0.f;
                vv.w = (l + 3 < L_IN) ? xb[(size_t)c * L_IN + l + 3] : 0.f;
            }
            x_s[c][1 + qq * 4] = vv.x;
            x_s[c][2 + qq * 4] = vv.y;
            x_s[c][3 + qq * 4] = vv.z;
            x_s[c][4 + qq * 4] = vv.w;
        }
        for (int c = t; c < C_IN; c += THREADS - 32) {
            int ll = l0 - 1;
            x_s[c][0]   = (ll >= 0) ? xb[(size_t)c * L_IN + ll] : 0.f;
            int lr = l0 + 128;
            x_s[c][129] = (lr < L_IN) ? xb[(size_t)c * L_IN + lr] : 0.f;
        }
    }
    __syncthreads();

    // ======== Phase 1: quad-split conv + shfl reduce + one quadratic form ========
    {
        const int pos = tid >> 2;                   // 0..127
        const int grp = tid & 3;                    // 0..3
        const int c0  = grp * C_PER_G;

        float v0 = 0.f, v1 = 0.f, v2 = 0.f, v3 = 0.f;
        #pragma unroll
        for (int ci = 0; ci < C_PER_G; ci++) {
            const int c = c0 + ci;
            float xa  = x_s[c][pos];                // l-1
            float xb1 = x_s[c][pos + 1];            // l
            float xc  = x_s[c][pos + 2];            // l+1
            const float4* wr = (const float4*)&w_s[c * 12];
            float4 w0 = wr[0], w1 = wr[1], w2 = wr[2];
            v0 += w0.x * xa + w1.x * xb1 + w2.x * xc;
            v1 += w0.y * xa + w1.y * xb1 + w2.y * xc;
            v2 += w0.z * xa + w1.z * xb1 + w2.z * xc;
            v3 += w0.w * xa + w1.w * xb1 + w2.w * xc;
        }
        v0 += __shfl_xor_sync(0xffffffffu, v0, 1);
        v1 += __shfl_xor_sync(0xffffffffu, v1, 1);
        v2 += __shfl_xor_sync(0xffffffffu, v2, 1);
        v3 += __shfl_xor_sync(0xffffffffu, v3, 1);
        v0 += __shfl_xor_sync(0xffffffffu, v0, 2);
        v1 += __shfl_xor_sync(0xffffffffu, v1, 2);
        v2 += __shfl_xor_sync(0xffffffffu, v2, 2);
        v3 += __shfl_xor_sync(0xffffffffu, v3, 2);

        v0 += bpre_s[0]; v1 += bpre_s[1]; v2 += bpre_s[2]; v3 += bpre_s[3];

        const float inv = __frcp_rn(v0 * v0 + v1 * v1 + v2 * v2 + v3 * v3);
        const float* Qr = &Q_s[grp][0];
        float s;
        s  = v0 * (Qr[0]  * v0 + Qr[1]  * v1 + Qr[2]  * v2 + Qr[3]  * v3);
        s += v1 * (Qr[4]  * v0 + Qr[5]  * v1 + Qr[6]  * v2 + Qr[7]  * v3);
        s += v2 * (Qr[8]  * v0 + Qr[9]  * v1 + Qr[10] * v2 + Qr[11] * v3);
        s += v3 * (Qr[12] * v0 + Qr[13] * v1 + Qr[14] * v2 + Qr[15] * v3);
        ez_s[pos][grp] = s * inv;
    }
    __syncthreads();

    // ======== Phase 2: 4->512 broadcast + streaming float4 stores (writer config) ====
    const int lane = tid & 31;
    const int wrp  = tid >> 5;                  // 0..15
    const int l4   = l0 + lane * 4;
    if (l4 >= L_IN) return;                     // L_IN % 4 == 0: no straddle

    const float4* ez4 = (const float4*)ez_s;
    const float4 e0 = ez4[lane * 4 + 0];
    const float4 e1 = ez4[lane * 4 + 1];
    const float4 e2 = ez4[lane * 4 + 2];
    const float4 e3 = ez4[lane * 4 + 3];

    float* outb = out + (size_t)b * OUT_CH * L_IN;

    #pragma unroll 8
    for (int o = wrp; o < OUT_CH; o += 16) {
        const float4 wp = __ldg((const float4*)(W_post + o * 4));
        const float  bp = __ldg(b_post + o);
        float4 r;
        r.x = fmaf(wp.x, e0.x, fmaf(wp.y, e0.y, fmaf(wp.z, e0.z, fmaf(wp.w, e0.w, bp))));
        r.y = fmaf(wp.x, e1.x, fmaf(wp.y, e1.y, fmaf(wp.z, e1.z, fmaf(wp.w, e1.w, bp))));
        r.z = fmaf(wp.x, e2.x, fmaf(wp.y, e2.y, fmaf(wp.z, e2.z, fmaf(wp.w, e2.w, bp))));
        r.w = fmaf(wp.x, e3.x, fmaf(wp.y, e3.y, fmaf(wp.z, e3.z, fmaf(wp.w, e3.w, bp))));
        __stcs((float4*)(outb + (size_t)o * L_IN + l4), r);
    }
}

extern "C" void kernel_launch(void* const* d_in, const int* in_sizes, int n_in,
                              void* d_out, int out_size)
{
    const float* x      = (const float*)d_in[0];
    const float* W_pre  = (const float*)d_in[1];
    const float* b_pre  = (const float*)d_in[2];
    const float* W_post = (const float*)d_in[3];
    const float* b_post = (const float*)d_in[4];
    const float* qw     = (const float*)d_in[5];
    float* out = (float*)d_out;

    const int B = in_sizes[0] / (C_IN * L_IN);                  // 32
    const int n_tiles = (L_IN + TILE_L - 1) / TILE_L;           // 24

    dim3 grid(n_tiles, B);
    qconv_fused<<<grid, THREADS>>>(x, W_pre, b_pre, W_post, b_post, qw, out);
}